// round 6
// baseline (speedup 1.0000x reference)
#include <cuda_runtime.h>
#include <cstdint>

// ---------------------------------------------------------------------------
// LinearFlow: out[t,n,i] = sum_j expm(t_k * A)[i,j] * x[n,j]
//   A = 0.5*((M+M0) - (M+M0)^T), 8x8 skew-symmetric, ||tA|| << 1
// Phase 1: Taylor-series expm for all 512 t  (tiny)
// Phase 2: apply E[t] to all 16384 rows of x -> 256 MB write (DRAM-bound)
// ---------------------------------------------------------------------------

#define MS        8
#define T_MAX     512
#define TT        8      // t-values per apply-block
#define NPR       4      // n-rows per thread (2 f32x2 pairs)
#define THREADS   256
#define KTERMS    10     // Taylor order; ||tA|| <= ~0.15 -> error ~1e-17

__device__ float g_E[T_MAX * MS * MS];   // E[t][i][j]

// ---- f32x2 helpers (packed fp32 pair in one 64-bit reg, sm_100+) ----------
__device__ __forceinline__ unsigned long long pack2(float lo, float hi) {
    unsigned long long r;
    asm("mov.b64 %0, {%1, %2};" : "=l"(r) : "f"(lo), "f"(hi));
    return r;
}
__device__ __forceinline__ unsigned long long fma2(unsigned long long a,
                                                   unsigned long long b,
                                                   unsigned long long c) {
    unsigned long long d;
    asm("fma.rn.f32x2 %0, %1, %2, %3;" : "=l"(d) : "l"(a), "l"(b), "l"(c));
    return d;
}
__device__ __forceinline__ void unpack2(unsigned long long v, float& lo, float& hi) {
    asm("mov.b64 {%0, %1}, %2;" : "=f"(lo), "=f"(hi) : "l"(v));
}

// ---------------------------------------------------------------------------
// Phase 1: E[t] = expm(t*A) via Taylor with shared-memory 8x8 matmuls.
// 64 threads per t (one per matrix element), 8 t per 512-thread block.
// P_1 = tA; P_k = P_{k-1} @ (tA) / k; E = I + sum_k P_k.
// ---------------------------------------------------------------------------
__global__ void expm_kernel(const float* __restrict__ t,
                            const float* __restrict__ M,
                            const float* __restrict__ M0,
                            int T) {
    __shared__ float sA[8][64];        // tA per t-slot
    __shared__ float sP[2][8][64];     // double-buffered power term

    const int tid = threadIdx.x;
    const int tt  = tid >> 6;          // 0..7: t slot within block
    const int e   = tid & 63;          // element index
    const int i   = e >> 3;
    const int j   = e & 7;
    const int tg  = blockIdx.x * 8 + tt;

    const float tv  = (tg < T) ? t[tg] : 0.0f;
    const float bij = M[i * 8 + j] + M0[i * 8 + j];
    const float bji = M[j * 8 + i] + M0[j * 8 + i];
    const float a   = 0.5f * (bij - bji) * tv;

    sA[tt][e]    = a;
    sP[0][tt][e] = a;
    float acc = ((i == j) ? 1.0f : 0.0f) + a;
    __syncthreads();

    int buf = 0;
    #pragma unroll
    for (int k = 2; k <= KTERMS; k++) {
        float c = 0.0f;
        #pragma unroll
        for (int m = 0; m < 8; m++)
            c = fmaf(sP[buf][tt][i * 8 + m], sA[tt][m * 8 + j], c);
        c *= (1.0f / (float)k);
        acc += c;
        sP[1 - buf][tt][e] = c;   // write other buffer; readers still on `buf`
        buf ^= 1;
        __syncthreads();          // publish new buffer before next iteration
    }

    if (tg < T) g_E[tg * 64 + e] = acc;
}

// ---------------------------------------------------------------------------
// Phase 2: out[t,n,:] = E[t] @ x[n,:] for TT t-values per block.
// Each thread owns 4 rows (2 f32x2 pairs). E is staged in smem as
// duplicated f32x2 pairs so one broadcast LDS.64 feeds both FMA2 lanes.
// ---------------------------------------------------------------------------
__global__ void __launch_bounds__(THREADS)
apply_kernel(const float* __restrict__ x,
             float* __restrict__ out,
             int N) {
    __shared__ unsigned long long sE2[TT][64];

    const int tid   = threadIdx.x;
    const int tbase = blockIdx.y * TT;

    // Stage E for this block's 8 t-values, duplicated into both pair lanes.
    #pragma unroll
    for (int k = tid; k < TT * 64; k += THREADS) {
        float ev = g_E[(tbase + (k >> 6)) * 64 + (k & 63)];
        sE2[k >> 6][k & 63] = pack2(ev, ev);
    }
    __syncthreads();

    // Rows handled by this thread: nbase + r*THREADS, r = 0..3
    const int nbase = blockIdx.x * (THREADS * NPR) + tid;

    // Load x rows, packed across the row-pair dimension.
    unsigned long long x2[2][8];
    #pragma unroll
    for (int p = 0; p < 2; p++) {
        const int rA = nbase + (2 * p)     * THREADS;
        const int rB = nbase + (2 * p + 1) * THREADS;
        float4 a0 = reinterpret_cast<const float4*>(x)[rA * 2];
        float4 a1 = reinterpret_cast<const float4*>(x)[rA * 2 + 1];
        float4 b0 = reinterpret_cast<const float4*>(x)[rB * 2];
        float4 b1 = reinterpret_cast<const float4*>(x)[rB * 2 + 1];
        x2[p][0] = pack2(a0.x, b0.x);  x2[p][1] = pack2(a0.y, b0.y);
        x2[p][2] = pack2(a0.z, b0.z);  x2[p][3] = pack2(a0.w, b0.w);
        x2[p][4] = pack2(a1.x, b1.x);  x2[p][5] = pack2(a1.y, b1.y);
        x2[p][6] = pack2(a1.z, b1.z);  x2[p][7] = pack2(a1.w, b1.w);
    }

    #pragma unroll 2
    for (int tt = 0; tt < TT; tt++) {
        unsigned long long o2[2][8];
        #pragma unroll
        for (int i = 0; i < 8; i++) { o2[0][i] = 0ull; o2[1][i] = 0ull; }

        #pragma unroll
        for (int i = 0; i < 8; i++) {
            #pragma unroll
            for (int j = 0; j < 8; j++) {
                unsigned long long e2 = sE2[tt][i * 8 + j];  // warp-broadcast
                o2[0][i] = fma2(e2, x2[0][j], o2[0][i]);
                o2[1][i] = fma2(e2, x2[1][j], o2[1][i]);
            }
        }

        const size_t tb = (size_t)(tbase + tt) * (size_t)N;
        #pragma unroll
        for (int p = 0; p < 2; p++) {
            const int rA = nbase + (2 * p)     * THREADS;
            const int rB = nbase + (2 * p + 1) * THREADS;
            float lo[8], hi[8];
            #pragma unroll
            for (int i = 0; i < 8; i++) unpack2(o2[p][i], lo[i], hi[i]);

            float4* oA = reinterpret_cast<float4*>(out + (tb + (size_t)rA) * 8);
            oA[0] = make_float4(lo[0], lo[1], lo[2], lo[3]);
            oA[1] = make_float4(lo[4], lo[5], lo[6], lo[7]);
            float4* oB = reinterpret_cast<float4*>(out + (tb + (size_t)rB) * 8);
            oB[0] = make_float4(hi[0], hi[1], hi[2], hi[3]);
            oB[1] = make_float4(hi[4], hi[5], hi[6], hi[7]);
        }
    }
}

// ---------------------------------------------------------------------------
extern "C" void kernel_launch(void* const* d_in, const int* in_sizes, int n_in,
                              void* d_out, int out_size) {
    const float* x  = (const float*)d_in[0];   // [N, 8]
    const float* t  = (const float*)d_in[1];   // [T]
    const float* M  = (const float*)d_in[2];   // [8, 8]
    const float* M0 = (const float*)d_in[3];   // [8, 8]
    float* out = (float*)d_out;                // [T, N, 8]

    const int N = in_sizes[0] / MS;            // 16384
    const int T = in_sizes[1];                 // 512

    // Phase 1: 8 t per block, 64 threads each.
    expm_kernel<<<(T + 7) / 8, 512>>>(t, M, M0, T);

    // Phase 2: grid (N / (256*4), T / 8)
    dim3 grid(N / (THREADS * NPR), T / TT);
    apply_kernel<<<grid, THREADS>>>(x, out, N);
}

// round 7
// speedup vs baseline: 1.4744x; 1.4744x over previous
#include <cuda_runtime.h>
#include <cstdint>

// ---------------------------------------------------------------------------
// LinearFlow: out[t,n,i] = sum_j expm(t_k * A)[i,j] * x[n,j]
//   A = 0.5*((M+M0) - (M+M0)^T), 8x8 skew-symmetric, ||tA|| <~ 0.15
//
// Phase 1: Taylor expm for all 512 t, output PRE-PACKED for phase 2:
//          g_Epk[tpair][j][i] = f32x2( E[2q][i][j], E[2q+1][i][j] )
// Phase 2: DRAM-bound 256 MB write. Layout chosen for:
//          - fully coalesced STG.128 (2 lanes per 32 B row)
//          - f32x2 FMA packing across t-pairs (halves FMA issue)
//          - low register count (x held once per thread across 64 t)
// ---------------------------------------------------------------------------

#define MS        8
#define T_MAX     512
#define TB_T      64     // t-values per apply block (32 t-pairs)
#define ROWS_B    128    // n-rows per apply block
#define THREADS   256
#define KTERMS    10     // Taylor order; error ~1e-17 << fp32 eps

// Packed E: [T/2][j][i] as (t_even, t_odd) f32x2 pairs. 128 KB.
__device__ unsigned long long g_Epk[(T_MAX / 2) * 64];

// ---- f32x2 helpers ---------------------------------------------------------
__device__ __forceinline__ unsigned long long pack2(float lo, float hi) {
    unsigned long long r;
    asm("mov.b64 %0, {%1, %2};" : "=l"(r) : "f"(lo), "f"(hi));
    return r;
}
__device__ __forceinline__ unsigned long long fma2(unsigned long long a,
                                                   unsigned long long b,
                                                   unsigned long long c) {
    unsigned long long d;
    asm("fma.rn.f32x2 %0, %1, %2, %3;" : "=l"(d) : "l"(a), "l"(b), "l"(c));
    return d;
}
__device__ __forceinline__ void unpack2(unsigned long long v, float& lo, float& hi) {
    asm("mov.b64 {%0, %1}, %2;" : "=f"(lo), "=f"(hi) : "l"(v));
}

// ---------------------------------------------------------------------------
// Phase 1: E[t] = expm(t*A), 64 threads per t, 8 t per block.
// P_1 = tA; P_k = P_{k-1} @ tA / k; E = I + sum P_k.
// Writes TRANSPOSED+PACKED layout for phase 2.
// ---------------------------------------------------------------------------
__global__ void expm_kernel(const float* __restrict__ t,
                            const float* __restrict__ M,
                            const float* __restrict__ M0,
                            int T) {
    __shared__ float sA[8][64];
    __shared__ float sP[2][8][64];

    const int tid = threadIdx.x;
    const int tt  = tid >> 6;
    const int e   = tid & 63;
    const int i   = e >> 3;
    const int j   = e & 7;
    const int tg  = blockIdx.x * 8 + tt;

    const float tv  = (tg < T) ? t[tg] : 0.0f;
    const float bij = M[i * 8 + j] + M0[i * 8 + j];
    const float bji = M[j * 8 + i] + M0[j * 8 + i];
    const float a   = 0.5f * (bij - bji) * tv;

    sA[tt][e]    = a;
    sP[0][tt][e] = a;
    float acc = ((i == j) ? 1.0f : 0.0f) + a;
    __syncthreads();

    int buf = 0;
    #pragma unroll
    for (int k = 2; k <= KTERMS; k++) {
        float c = 0.0f;
        #pragma unroll
        for (int m = 0; m < 8; m++)
            c = fmaf(sP[buf][tt][i * 8 + m], sA[tt][m * 8 + j], c);
        c *= (1.0f / (float)k);
        acc += c;
        sP[1 - buf][tt][e] = c;
        buf ^= 1;
        __syncthreads();
    }

    if (tg < T) {
        // packed layout: float view of g_Epk, index = (pair*64 + j*8 + i)*2 + (tg&1)
        float* dst = reinterpret_cast<float*>(g_Epk);
        dst[(((tg >> 1) * 64) + j * 8 + i) * 2 + (tg & 1)] = acc;
    }
}

// ---------------------------------------------------------------------------
// Phase 2.
// Warp covers 16 rows: lane L -> row rb16 + (L>>1), half h = L&1,
// computing components i in [4h, 4h+4). f32x2 packs (t_even, t_odd).
// Stores: lane L writes float4 at f4_index = (t*N + rb16)*2 + L  -> 512 B
// contiguous per warp store, perfectly coalesced.
// ---------------------------------------------------------------------------
__global__ void __launch_bounds__(THREADS)
apply_kernel(const float* __restrict__ x,
             float* __restrict__ out,
             int N) {
    __shared__ unsigned long long sE[(TB_T / 2) * 64];   // 16 KB

    const int tid    = threadIdx.x;
    const int tpair0 = blockIdx.y * (TB_T / 2);

    // Stage packed E slab: straight coalesced copy (1024 float4).
    {
        const float4* src = reinterpret_cast<const float4*>(g_Epk + (size_t)tpair0 * 64);
        float4* dst = reinterpret_cast<float4*>(sE);
        #pragma unroll
        for (int k = 0; k < ((TB_T / 2) * 64 * 8 / 16) / THREADS; k++)   // 4
            dst[tid + k * THREADS] = src[tid + k * THREADS];
    }

    const int warp = tid >> 5;
    const int lane = tid & 31;
    const int h    = lane & 1;
    const int rb16 = blockIdx.x * ROWS_B + warp * 16;
    const int row  = rb16 + (lane >> 1);

    // Load this lane's x row (both half-lanes load the same row: L1 broadcast),
    // duplicate-pack into f32x2 so one reg feeds both t-lanes of fma2.
    const float4* xp = reinterpret_cast<const float4*>(x) + (size_t)row * 2;
    float4 q0 = xp[0], q1 = xp[1];
    unsigned long long x2[8];
    x2[0] = pack2(q0.x, q0.x);  x2[1] = pack2(q0.y, q0.y);
    x2[2] = pack2(q0.z, q0.z);  x2[3] = pack2(q0.w, q0.w);
    x2[4] = pack2(q1.x, q1.x);  x2[5] = pack2(q1.y, q1.y);
    x2[6] = pack2(q1.z, q1.z);  x2[7] = pack2(q1.w, q1.w);

    __syncthreads();

    const unsigned long long* eBase = sE + h * 4;        // i-offset = 4h
    float4* outf4 = reinterpret_cast<float4*>(out);
    const size_t f4row  = (size_t)rb16 * 2 + lane;       // + t*2N per t-plane
    const size_t f4stepT = (size_t)2 * N;                // f4 per t
    size_t f4t0 = (size_t)(tpair0 * 2) * f4stepT + f4row;

    #pragma unroll 2
    for (int tq = 0; tq < TB_T / 2; tq++) {
        const unsigned long long* e = eBase + tq * 64;
        unsigned long long o0 = 0ull, o1 = 0ull, o2 = 0ull, o3 = 0ull;

        #pragma unroll
        for (int j = 0; j < 8; j++) {
            // 2x LDS.128: e2 for i = 4h+0..3 (broadcast within half-lanes)
            ulonglong2 eab = *reinterpret_cast<const ulonglong2*>(e + j * 8);
            ulonglong2 ecd = *reinterpret_cast<const ulonglong2*>(e + j * 8 + 2);
            o0 = fma2(eab.x, x2[j], o0);
            o1 = fma2(eab.y, x2[j], o1);
            o2 = fma2(ecd.x, x2[j], o2);
            o3 = fma2(ecd.y, x2[j], o3);
        }

        float a0, b0, a1, b1, a2, b2, a3, b3;
        unpack2(o0, a0, b0);  unpack2(o1, a1, b1);
        unpack2(o2, a2, b2);  unpack2(o3, a3, b3);

        outf4[f4t0]            = make_float4(a0, a1, a2, a3);   // t even
        outf4[f4t0 + f4stepT]  = make_float4(b0, b1, b2, b3);   // t odd
        f4t0 += 2 * f4stepT;
    }
}

// ---------------------------------------------------------------------------
extern "C" void kernel_launch(void* const* d_in, const int* in_sizes, int n_in,
                              void* d_out, int out_size) {
    const float* x  = (const float*)d_in[0];   // [N, 8]
    const float* t  = (const float*)d_in[1];   // [T]
    const float* M  = (const float*)d_in[2];   // [8, 8]
    const float* M0 = (const float*)d_in[3];   // [8, 8]
    float* out = (float*)d_out;                // [T, N, 8]

    const int N = in_sizes[0] / MS;            // 16384
    const int T = in_sizes[1];                 // 512

    expm_kernel<<<(T + 7) / 8, 512>>>(t, M, M0, T);

    dim3 grid(N / ROWS_B, T / TB_T);           // (128, 8)
    apply_kernel<<<grid, THREADS>>>(x, out, N);
}